// round 7
// baseline (speedup 1.0000x reference)
#include <cuda_runtime.h>
#include <cstdint>
#include <math.h>

// ---------------- problem constants ----------------
#define TT 2048   // tokens
#define HH 2048   // hidden
#define II 5632   // intermediate
#define EE 8      // experts
#define CAP 2048  // per-expert row capacity

// ---------------- scratch ----------------
__device__ int   g_count[EE];
__device__ int   g_row_token[EE * CAP];
__device__ int   g_token_row[TT * 2];
__device__ float g_token_w[TT * 2];
__device__ float g_act[(size_t)EE * CAP * II];   // 369MB
__device__ float g_y  [(size_t)EE * CAP * HH];   // 134MB

// ---------------- helpers ----------------
__device__ __forceinline__ uint32_t smem_to_u32(const void* p) {
    uint32_t a;
    asm("{ .reg .u64 t; cvta.to.shared.u64 t, %1; cvt.u32.u64 %0, t; }" : "=r"(a) : "l"(p));
    return a;
}
__device__ __forceinline__ void cp_async16(uint32_t dst, const void* src) {
    asm volatile("cp.async.cg.shared.global [%0], [%1], 16;" :: "r"(dst), "l"(src));
}
#define CP_COMMIT() asm volatile("cp.async.commit_group;" ::: "memory")
#define CP_WAIT2()  asm volatile("cp.async.wait_group 2;" ::: "memory")

// D = A(16x8) * B(8x8) + D, tf32 inputs, f32 accumulate
__device__ __forceinline__ void mma_tf32(float* c, const uint32_t* a, const uint32_t* b) {
    asm volatile(
        "mma.sync.aligned.m16n8k8.row.col.f32.tf32.tf32.f32 "
        "{%0,%1,%2,%3}, {%4,%5,%6,%7}, {%8,%9}, {%0,%1,%2,%3};"
        : "+f"(c[0]), "+f"(c[1]), "+f"(c[2]), "+f"(c[3])
        : "r"(a[0]), "r"(a[1]), "r"(a[2]), "r"(a[3]), "r"(b[0]), "r"(b[1]));
}
// round-half-up to tf32 boundary (HW truncates low 13 mantissa bits)
#define TF32_RND(u) ((u) + 0x1000u)

// ---------------- init ----------------
__global__ void init_kernel() {
    int i = blockIdx.x * blockDim.x + threadIdx.x;
    if (i < EE) g_count[i] = 0;
    if (i < EE * CAP) g_row_token[i] = 0;
}

// ---------------- router ----------------
__global__ void router_kernel(const float* __restrict__ x, const float* __restrict__ gw) {
    int t = blockIdx.x;
    const float* xr = x + (size_t)t * HH;
    float acc[EE];
#pragma unroll
    for (int e = 0; e < EE; e++) acc[e] = 0.f;
    for (int k = threadIdx.x; k < HH; k += blockDim.x) {
        float xv = xr[k];
#pragma unroll
        for (int e = 0; e < EE; e++) acc[e] += xv * gw[e * HH + k];
    }
    __shared__ float red[EE][128];
#pragma unroll
    for (int e = 0; e < EE; e++) red[e][threadIdx.x] = acc[e];
    __syncthreads();
    for (int s = 64; s > 0; s >>= 1) {
        if (threadIdx.x < s) {
#pragma unroll
            for (int e = 0; e < EE; e++) red[e][threadIdx.x] += red[e][threadIdx.x + s];
        }
        __syncthreads();
    }
    if (threadIdx.x == 0) {
        float l[EE];
#pragma unroll
        for (int e = 0; e < EE; e++) l[e] = red[e][0];
        int i0 = 0;
#pragma unroll
        for (int e = 1; e < EE; e++) if (l[e] > l[i0]) i0 = e;
        int i1 = (i0 == 0) ? 1 : 0;
#pragma unroll
        for (int e = 0; e < EE; e++) if (e != i0 && l[e] > l[i1]) i1 = e;
        float w0 = 1.f / (1.f + expf(l[i1] - l[i0]));
        float w1 = 1.f - w0;
        int p0 = atomicAdd(&g_count[i0], 1);
        int p1 = atomicAdd(&g_count[i1], 1);
        g_row_token[i0 * CAP + p0] = t;
        g_row_token[i1 * CAP + p1] = t;
        g_token_row[t * 2 + 0] = i0 * CAP + p0;
        g_token_row[t * 2 + 1] = i1 * CAP + p1;
        g_token_w[t * 2 + 0] = w0;
        g_token_w[t * 2 + 1] = w1;
    }
}

// ---------------- TF32 mma.sync GEMM, cp.async 4-stage pipeline ----------------
// C[m,n] = sum_k A[m,k] * W[e][n,k]; BM=BN=128, BK=16, 256 threads (8 warps, 2Mx4N).
// GATHER=1: A rows gathered from X via g_row_token.
// MODE 0: gate -> g_act raw. MODE 1: up -> g_act = silu(g_act)*acc. MODE 2: down -> g_y raw.
#define SPITCH 20                     // smem row stride in u32 (16 data + 4 pad)
#define STG_U32  (2 * 128 * SPITCH)   // u32 per stage (A then B)
#define STG_B    (STG_U32 * 4)        // 20480 bytes per stage
#define B_OFF_U32 (128 * SPITCH)      // B offset within stage (u32)
#define NSTAGE 4
#define SMEM_BYTES (NSTAGE * STG_B)   // 81920

template <int GATHER, int MODE>
__global__ void __launch_bounds__(256, 2)
mma_gemm_kernel(const float* __restrict__ X, const float* __restrict__ Wglob) {
    constexpr int N  = (MODE == 2) ? HH : II;
    constexpr int Kd = (MODE == 2) ? II : HH;
    constexpr int NT = Kd / 16;

    extern __shared__ uint32_t smem[];
    const uint32_t smem_base = smem_to_u32(smem);

    const int e   = blockIdx.z;
    const int cnt = g_count[e];
    const int m0  = blockIdx.y * 128;
    if (m0 >= cnt) return;
    const int n0  = blockIdx.x * 128;

    const int tid  = threadIdx.x;
    const int lane = tid & 31;
    const int wid  = tid >> 5;
    const int wm   = wid >> 2;   // 0..1  (M)
    const int wn   = wid & 3;    // 0..3  (N)
    const int gid  = lane >> 2;  // 0..7
    const int tig  = lane & 3;   // 0..3

    const float* W = Wglob + (size_t)e * N * Kd;
    float* C = (MODE == 2) ? g_y : g_act;

    // ---- cp.async mapping: thread -> one A row + one B row, 32B (2x16B) per stage ----
    const int lrow = tid >> 1;          // 0..127
    const int half = tid & 1;           // 0,1 -> k offset 0 or 8 floats
    size_t arow;
    if (GATHER) arow = (size_t)g_row_token[e * CAP + m0 + lrow];
    else        arow = (size_t)(e * CAP + m0 + lrow);
    const float* Abase = GATHER ? X : g_act;
    const float* aPtr = Abase + arow * Kd + half * 8;
    const float* bPtr = W + (size_t)(n0 + lrow) * Kd + half * 8;
    const uint32_t sA = smem_base + (uint32_t)(lrow * SPITCH + half * 8) * 4;
    const uint32_t sB = sA + B_OFF_U32 * 4;

    // ---- prologue: stages 0..2 ----
#pragma unroll
    for (int s = 0; s < NSTAGE - 1; ++s) {
        const uint32_t so = (uint32_t)s * STG_B;
        const int k0 = s * 16;
        cp_async16(sA + so,      aPtr + k0);
        cp_async16(sA + so + 16, aPtr + k0 + 4);
        cp_async16(sB + so,      bPtr + k0);
        cp_async16(sB + so + 16, bPtr + k0 + 4);
        CP_COMMIT();
    }

    float c[4][4][4];
#pragma unroll
    for (int mt = 0; mt < 4; mt++)
#pragma unroll
        for (int nt = 0; nt < 4; nt++)
#pragma unroll
            for (int i = 0; i < 4; i++) c[mt][nt][i] = 0.f;

    const int aRowBase = wm * 64 + gid;
    const int bRowBase = wn * 32 + gid;

    for (int it = 0; it < NT; ++it) {
        CP_WAIT2();
        __syncthreads();

        const uint32_t* Ac = smem + (size_t)(it & (NSTAGE - 1)) * STG_U32;
        const uint32_t* Bc = Ac + B_OFF_U32;
#pragma unroll
        for (int K = 0; K < 2; K++) {
            const int kc = K * 8 + tig;
            uint32_t af[4][4];
#pragma unroll
            for (int mt = 0; mt < 4; mt++) {
                const int r = (aRowBase + mt * 16) * SPITCH + kc;
                af[mt][0] = TF32_RND(Ac[r]);
                af[mt][1] = TF32_RND(Ac[r + 8 * SPITCH]);
                af[mt][2] = TF32_RND(Ac[r + 4]);
                af[mt][3] = TF32_RND(Ac[r + 8 * SPITCH + 4]);
            }
            uint32_t bf[4][2];
#pragma unroll
            for (int nt = 0; nt < 4; nt++) {
                const int r = (bRowBase + nt * 8) * SPITCH + kc;
                bf[nt][0] = TF32_RND(Bc[r]);
                bf[nt][1] = TF32_RND(Bc[r + 4]);
            }
#pragma unroll
            for (int mt = 0; mt < 4; mt++)
#pragma unroll
                for (int nt = 0; nt < 4; nt++)
                    mma_tf32(c[mt][nt], af[mt], bf[nt]);
        }

        // issue stage it+3
        if (it + NSTAGE - 1 < NT) {
            const uint32_t so = (uint32_t)((it + NSTAGE - 1) & (NSTAGE - 1)) * STG_B;
            const int k0 = (it + NSTAGE - 1) * 16;
            cp_async16(sA + so,      aPtr + k0);
            cp_async16(sA + so + 16, aPtr + k0 + 4);
            cp_async16(sB + so,      bPtr + k0);
            cp_async16(sB + so + 16, bPtr + k0 + 4);
        }
        CP_COMMIT();
    }

    // ---- epilogue ----
#pragma unroll
    for (int mt = 0; mt < 4; mt++) {
        const int row = m0 + wm * 64 + mt * 16 + gid;
#pragma unroll
        for (int nt = 0; nt < 4; nt++) {
            const int col = n0 + wn * 32 + nt * 8 + 2 * tig;
            size_t b0 = (size_t)(e * CAP + row) * N + col;
            size_t b1 = b0 + (size_t)8 * N;
            float2 v0 = make_float2(c[mt][nt][0], c[mt][nt][1]);
            float2 v1 = make_float2(c[mt][nt][2], c[mt][nt][3]);
            if (MODE == 1) {
                float2 ga = *(const float2*)&C[b0];
                float2 gb = *(const float2*)&C[b1];
                v0.x *= ga.x / (1.f + expf(-ga.x));
                v0.y *= ga.y / (1.f + expf(-ga.y));
                v1.x *= gb.x / (1.f + expf(-gb.x));
                v1.y *= gb.y / (1.f + expf(-gb.y));
            }
            *(float2*)&C[b0] = v0;
            *(float2*)&C[b1] = v1;
        }
    }
}

// ---------------- combine ----------------
__global__ void combine_kernel(float* __restrict__ out) {
    int idx = blockIdx.x * blockDim.x + threadIdx.x;
    if (idx >= TT * HH) return;
    int t = idx >> 11;
    int h = idx & (HH - 1);
    int r0 = g_token_row[t * 2 + 0];
    int r1 = g_token_row[t * 2 + 1];
    float w0 = g_token_w[t * 2 + 0];
    float w1 = g_token_w[t * 2 + 1];
    out[idx] = w0 * g_y[(size_t)r0 * HH + h] + w1 * g_y[(size_t)r1 * HH + h];
}

// ---------------- launch ----------------
extern "C" void kernel_launch(void* const* d_in, const int* in_sizes, int n_in,
                              void* d_out, int out_size) {
    const float* x  = (const float*)d_in[0];
    const float* gw = (const float*)d_in[1];
    const float* wg = (const float*)d_in[2];
    const float* wu = (const float*)d_in[3];
    const float* wd = (const float*)d_in[4];
    float* out = (float*)d_out;
    (void)in_sizes; (void)n_in; (void)out_size;

    static int smem_set = 0;
    if (!smem_set) {
        cudaFuncSetAttribute(mma_gemm_kernel<1, 0>, cudaFuncAttributeMaxDynamicSharedMemorySize, SMEM_BYTES);
        cudaFuncSetAttribute(mma_gemm_kernel<1, 1>, cudaFuncAttributeMaxDynamicSharedMemorySize, SMEM_BYTES);
        cudaFuncSetAttribute(mma_gemm_kernel<0, 2>, cudaFuncAttributeMaxDynamicSharedMemorySize, SMEM_BYTES);
        smem_set = 1;
    }

    init_kernel<<<64, 256>>>();
    router_kernel<<<TT, 128>>>(x, gw);

    dim3 g1(II / 128, CAP / 128, EE);   // (44,16,8)
    mma_gemm_kernel<1, 0><<<g1, 256, SMEM_BYTES>>>(x, wg);   // g = Xe @ Wg^T
    mma_gemm_kernel<1, 1><<<g1, 256, SMEM_BYTES>>>(x, wu);   // act = silu(g) * (Xe @ Wu^T)

    dim3 g2(HH / 128, CAP / 128, EE);   // (16,16,8)
    mma_gemm_kernel<0, 2><<<g2, 256, SMEM_BYTES>>>(nullptr, wd);  // y = act @ Wd^T

    combine_kernel<<<(TT * HH + 255) / 256, 256>>>(out);
}